// round 1
// baseline (speedup 1.0000x reference)
#include <cuda_runtime.h>

#define N_NODES 4096
#define N_CHILD 16384
#define DEGREE  64
#define BATCH   128
#define NNZ     (N_NODES * DEGREE)

// Scratch (device globals — no allocation allowed in kernel_launch)
__device__ float g_E[(size_t)N_CHILD * BATCH];   // E_T[c][b] = exp(child_ll[b][c]), 8 MB
__device__ float g_Wn[NNZ];                      // normalized exp(log_w) per node, 1 MB

// ---------------------------------------------------------------------------
// Kernel 1: exp + transpose.  child_ll is [B, C] row-major; produce E_T [C, B]
// so that per-edge gathers in the main kernel are contiguous 512B rows.
// ---------------------------------------------------------------------------
__global__ void exp_transpose_kernel(const float* __restrict__ child_ll) {
    __shared__ float tile[32][33];
    const int c0 = blockIdx.x * 32;
    const int b0 = blockIdx.y * 32;
    const int x = threadIdx.x, y = threadIdx.y;  // 32 x 8
#pragma unroll
    for (int i = 0; i < 32; i += 8)
        tile[y + i][x] = child_ll[(size_t)(b0 + y + i) * N_CHILD + (c0 + x)];
    __syncthreads();
#pragma unroll
    for (int i = 0; i < 32; i += 8)
        g_E[(size_t)(c0 + y + i) * BATCH + (b0 + x)] = __expf(tile[x][y + i]);
}

// ---------------------------------------------------------------------------
// Kernel 2: per-node normalized weights  Wn[e] = exp(lw[e]) / sum_node exp(lw)
// One warp per node (64 edges, 2 per lane), warp-shuffle reduction.
// Folding the normalization here removes log_z from the main kernel entirely.
// ---------------------------------------------------------------------------
__global__ void norm_w_kernel(const float* __restrict__ log_w) {
    const int node = blockIdx.x;
    const int lane = threadIdx.x;           // 32 threads
    const int base = node * DEGREE;
    float w0 = __expf(log_w[base + lane]);
    float w1 = __expf(log_w[base + 32 + lane]);
    float s = w0 + w1;
#pragma unroll
    for (int o = 16; o; o >>= 1) s += __shfl_xor_sync(0xffffffffu, s, o);
    const float inv = 1.0f / s;
    g_Wn[base + lane]      = w0 * inv;
    g_Wn[base + 32 + lane] = w1 * inv;
}

// ---------------------------------------------------------------------------
// Kernel 3: main gather-reduce.  One warp per node; each lane owns 4 batches
// (float4).  64 coalesced 512B gathers per node from L2-resident E_T.
//   out[b][n] = log( sum_e Wn[e] * E_T[cols[e]][b] )
// ---------------------------------------------------------------------------
__global__ void __launch_bounds__(128) sum_nodes_kernel(
    const int* __restrict__ cols, float* __restrict__ out) {
    const int wid  = threadIdx.x >> 5;
    const int lane = threadIdx.x & 31;
    const int node = blockIdx.x * 4 + wid;

    __shared__ float s_w[4][64];
    __shared__ int   s_c[4][64];

    const int base = node * DEGREE;
    s_w[wid][lane]      = g_Wn[base + lane];
    s_w[wid][lane + 32] = g_Wn[base + 32 + lane];
    s_c[wid][lane]      = cols[base + lane];
    s_c[wid][lane + 32] = cols[base + 32 + lane];
    __syncwarp();

    float4 a0 = make_float4(0.f, 0.f, 0.f, 0.f);
    float4 a1 = make_float4(0.f, 0.f, 0.f, 0.f);

#pragma unroll 8
    for (int e = 0; e < DEGREE; e += 2) {
        const int   c0 = s_c[wid][e];
        const int   c1 = s_c[wid][e + 1];
        const float w0 = s_w[wid][e];
        const float w1 = s_w[wid][e + 1];
        const float4 v0 = *reinterpret_cast<const float4*>(
            &g_E[(size_t)c0 * BATCH + lane * 4]);
        const float4 v1 = *reinterpret_cast<const float4*>(
            &g_E[(size_t)c1 * BATCH + lane * 4]);
        a0.x = fmaf(w0, v0.x, a0.x);
        a0.y = fmaf(w0, v0.y, a0.y);
        a0.z = fmaf(w0, v0.z, a0.z);
        a0.w = fmaf(w0, v0.w, a0.w);
        a1.x = fmaf(w1, v1.x, a1.x);
        a1.y = fmaf(w1, v1.y, a1.y);
        a1.z = fmaf(w1, v1.z, a1.z);
        a1.w = fmaf(w1, v1.w, a1.w);
    }

    const float rx = a0.x + a1.x;
    const float ry = a0.y + a1.y;
    const float rz = a0.z + a1.z;
    const float rw = a0.w + a1.w;

    const int b = lane * 4;
    const size_t o = (size_t)b * N_NODES + node;
    out[o]               = __logf(rx);
    out[o +     N_NODES] = __logf(ry);
    out[o + 2 * N_NODES] = __logf(rz);
    out[o + 3 * N_NODES] = __logf(rw);
}

// ---------------------------------------------------------------------------
extern "C" void kernel_launch(void* const* d_in, const int* in_sizes, int n_in,
                              void* d_out, int out_size) {
    const float* child_ll = (const float*)d_in[0];  // [128, 16384] f32
    const float* log_w    = (const float*)d_in[1];  // [262144] f32
    // d_in[2] = rows: structurally repeat(arange(4096), 64) — not needed
    const int*   cols     = (const int*)d_in[3];    // [262144] i32
    float*       out      = (float*)d_out;          // [128, 4096] f32

    dim3 tb(32, 8);
    dim3 tg(N_CHILD / 32, BATCH / 32);
    exp_transpose_kernel<<<tg, tb>>>(child_ll);
    norm_w_kernel<<<N_NODES, 32>>>(log_w);
    sum_nodes_kernel<<<N_NODES / 4, 128>>>(cols, out);
}

// round 2
// speedup vs baseline: 1.4147x; 1.4147x over previous
#include <cuda_runtime.h>
#include <cuda_fp16.h>

#define N_NODES 4096
#define N_CHILD 16384
#define DEGREE  64
#define BATCH   128
#define NNZ     (N_NODES * DEGREE)

// Scratch: E_T[c][b] = exp(child_ll[b][c]) in fp16 (4 MB, L2-resident)
__device__ __half g_Eh[(size_t)N_CHILD * BATCH];

// ---------------------------------------------------------------------------
// Kernel 1: exp + transpose + fp16 convert.
// child_ll [B=128, C=16384] f32 row-major  ->  g_Eh [C, B] fp16.
// Tile 64c x 64b, float4 reads, uint4 (8-half) writes, smem transpose.
// ---------------------------------------------------------------------------
__global__ void __launch_bounds__(256) exp_tr_kernel(
    const float* __restrict__ child_ll) {
    __shared__ float tile[64][65];
    const int c0 = blockIdx.x * 64;
    const int b0 = blockIdx.y * 64;

    // Load phase: 64 rows (b) x 16 float4 (c). 4 float4 per thread.
    const int q  = threadIdx.x & 15;   // float4 index along c
    const int r0 = threadIdx.x >> 4;   // row (b) 0..15
#pragma unroll
    for (int rr = 0; rr < 64; rr += 16) {
        const int r = r0 + rr;
        const float4 v = *reinterpret_cast<const float4*>(
            &child_ll[(size_t)(b0 + r) * N_CHILD + c0 + q * 4]);
        tile[q * 4 + 0][r] = v.x;
        tile[q * 4 + 1][r] = v.y;
        tile[q * 4 + 2][r] = v.z;
        tile[q * 4 + 3][r] = v.w;
    }
    __syncthreads();

    // Store phase: per child c, 64 batches fp16 = 128B. Thread writes uint4
    // (8 halves); 4 threads x 2 iterations cover one child row.
    const int c = threadIdx.x >> 2;    // 0..63
    const int s = threadIdx.x & 3;     // 0..3
#pragma unroll
    for (int h = 0; h < 2; h++) {
        const int b = s * 8 + h * 32;
        __half2 hv[4];
#pragma unroll
        for (int j = 0; j < 4; j++) {
            const float f0 = __expf(tile[c][b + 2 * j]);
            const float f1 = __expf(tile[c][b + 2 * j + 1]);
            hv[j] = __floats2half2_rn(f0, f1);
        }
        *reinterpret_cast<uint4*>(&g_Eh[(size_t)(c0 + c) * BATCH + b0 + b]) =
            *reinterpret_cast<const uint4*>(hv);
    }
}

// ---------------------------------------------------------------------------
// Kernel 2: fused weight-normalization + gather-reduce + coalesced output.
// One warp per node (8 nodes / 256-thread block). Each lane owns 4 batches.
//   out[b][n] = log( sum_e (exp(lw_e)/sum exp(lw)) * E_T[cols[e]][b] )
// Output staged in smem so stores are full 32B sectors (8 nodes contiguous).
// ---------------------------------------------------------------------------
__global__ void __launch_bounds__(256) sum_nodes_kernel(
    const float* __restrict__ log_w, const int* __restrict__ cols,
    float* __restrict__ out) {
    const int wid   = threadIdx.x >> 5;       // 0..7
    const int lane  = threadIdx.x & 31;
    const int node0 = blockIdx.x * 8;
    const int node  = node0 + wid;
    const int base  = node * DEGREE;

    __shared__ float s_w[8][64];
    __shared__ int   s_c[8][64];
    __shared__ float s_o[128][9];             // [batch][node-in-block], padded

    // Normalized weights (fused norm_w): warp shuffle reduction over 64 edges.
    const float w0 = __expf(log_w[base + lane]);
    const float w1 = __expf(log_w[base + 32 + lane]);
    float ssum = w0 + w1;
#pragma unroll
    for (int o = 16; o; o >>= 1) ssum += __shfl_xor_sync(0xffffffffu, ssum, o);
    const float inv = 1.0f / ssum;
    s_w[wid][lane]      = w0 * inv;
    s_w[wid][lane + 32] = w1 * inv;
    s_c[wid][lane]      = cols[base + lane];
    s_c[wid][lane + 32] = cols[base + 32 + lane];
    __syncwarp();

    float a0x = 0.f, a0y = 0.f, a0z = 0.f, a0w = 0.f;
    float a1x = 0.f, a1y = 0.f, a1z = 0.f, a1w = 0.f;

#pragma unroll 4
    for (int e = 0; e < DEGREE; e += 2) {
        const int   c0 = s_c[wid][e];
        const int   c1 = s_c[wid][e + 1];
        const float we0 = s_w[wid][e];
        const float we1 = s_w[wid][e + 1];
        // 4 halves per lane, 8B load; warp reads 256B contiguous per edge.
        const uint2 p0 = *reinterpret_cast<const uint2*>(
            &g_Eh[(size_t)c0 * BATCH + lane * 4]);
        const uint2 p1 = *reinterpret_cast<const uint2*>(
            &g_Eh[(size_t)c1 * BATCH + lane * 4]);
        const float2 f00 = __half22float2(*reinterpret_cast<const __half2*>(&p0.x));
        const float2 f01 = __half22float2(*reinterpret_cast<const __half2*>(&p0.y));
        const float2 f10 = __half22float2(*reinterpret_cast<const __half2*>(&p1.x));
        const float2 f11 = __half22float2(*reinterpret_cast<const __half2*>(&p1.y));
        a0x = fmaf(we0, f00.x, a0x);
        a0y = fmaf(we0, f00.y, a0y);
        a0z = fmaf(we0, f01.x, a0z);
        a0w = fmaf(we0, f01.y, a0w);
        a1x = fmaf(we1, f10.x, a1x);
        a1y = fmaf(we1, f10.y, a1y);
        a1z = fmaf(we1, f11.x, a1z);
        a1w = fmaf(we1, f11.y, a1w);
    }

    const int b = lane * 4;
    s_o[b + 0][wid] = __logf(a0x + a1x);
    s_o[b + 1][wid] = __logf(a0y + a1y);
    s_o[b + 2][wid] = __logf(a0z + a1z);
    s_o[b + 3][wid] = __logf(a0w + a1w);
    __syncthreads();

    // Coalesced output: thread t writes float4 -> out[bb][node0 + h*4 .. +3].
    const int bb = threadIdx.x >> 1;
    const int h  = threadIdx.x & 1;
    const float4 v = make_float4(s_o[bb][h * 4 + 0], s_o[bb][h * 4 + 1],
                                 s_o[bb][h * 4 + 2], s_o[bb][h * 4 + 3]);
    *reinterpret_cast<float4*>(&out[(size_t)bb * N_NODES + node0 + h * 4]) = v;
}

// ---------------------------------------------------------------------------
extern "C" void kernel_launch(void* const* d_in, const int* in_sizes, int n_in,
                              void* d_out, int out_size) {
    const float* child_ll = (const float*)d_in[0];  // [128, 16384] f32
    const float* log_w    = (const float*)d_in[1];  // [262144] f32
    // d_in[2] = rows: structurally repeat(arange(4096), 64) — unused
    const int*   cols     = (const int*)d_in[3];    // [262144] i32
    float*       out      = (float*)d_out;          // [128, 4096] f32

    dim3 tg(N_CHILD / 64, BATCH / 64);              // (256, 2)
    exp_tr_kernel<<<tg, 256>>>(child_ll);
    sum_nodes_kernel<<<N_NODES / 8, 256>>>(log_w, cols, out);
}